// round 7
// baseline (speedup 1.0000x reference)
#include <cuda_runtime.h>
#include <cuda_bf16.h>
#include <cstdint>
#include <cstddef>

#define BATCH 64
#define TLEN  1024
#define EDIM  512
#define HDIM  256
#define NROWS (BATCH*TLEN)   /* 65536 */

// ---------------- scratch (device globals: allocation-free rule) ----------------
__device__ float          g_x  [(size_t)NROWS * EDIM];  // f32 activations (layer-1 out, head in)
__device__ float          g_xp [(size_t)NROWS * EDIM];  // input-projection results
__device__ float          g_hxp[(size_t)NROWS * 16];    // head projections (13 used)
__device__ __nv_bfloat16  g_ahi[(size_t)NROWS * EDIM];  // A hi (bf16 split of GEMM input)
__device__ __nv_bfloat16  g_alo[(size_t)NROWS * EDIM];  // A lo
__device__ __nv_bfloat16  g_bhi[(size_t)EDIM * EDIM];   // W hi (512x512)
__device__ __nv_bfloat16  g_blo[(size_t)EDIM * EDIM];   // W lo

// ---------------- packed f32x2 helpers ----------------
__device__ __forceinline__ unsigned long long pack2(float lo, float hi) {
    unsigned long long r;
    asm("mov.b64 %0, {%1,%2};" : "=l"(r) : "f"(lo), "f"(hi));
    return r;
}
__device__ __forceinline__ float2 unpack2(unsigned long long v) {
    float2 r;
    asm("mov.b64 {%0,%1}, %2;" : "=f"(r.x), "=f"(r.y) : "l"(v));
    return r;
}
__device__ __forceinline__ void fma2(unsigned long long &d, unsigned long long a, unsigned long long b) {
    asm("fma.rn.f32x2 %0, %1, %2, %0;" : "+l"(d) : "l"(a), "l"(b));
}

// ---------------- small helpers ----------------
__device__ __forceinline__ uint32_t smem_u32(const void* p) {
    uint32_t a;
    asm("{ .reg .u64 t; cvta.to.shared.u64 t, %1; cvt.u32.u64 %0, t; }" : "=r"(a) : "l"(p));
    return a;
}
__device__ __forceinline__ uint32_t lds32(uint32_t a) {
    uint32_t v; asm("ld.shared.b32 %0, [%1];" : "=r"(v) : "r"(a)); return v;
}
__device__ __forceinline__ void cpasync16(uint32_t dst, const void* src) {
    asm volatile("cp.async.cg.shared.global [%0], [%1], 16;" :: "r"(dst), "l"(src));
}
__device__ __forceinline__ void mma16816(float* d, uint32_t a0, uint32_t a1, uint32_t a2,
                                         uint32_t a3, uint32_t b0, uint32_t b1) {
    asm("mma.sync.aligned.m16n8k16.row.col.f32.bf16.bf16.f32 "
        "{%0,%1,%2,%3}, {%4,%5,%6,%7}, {%8,%9}, {%0,%1,%2,%3};"
        : "+f"(d[0]), "+f"(d[1]), "+f"(d[2]), "+f"(d[3])
        : "r"(a0), "r"(a1), "r"(a2), "r"(a3), "r"(b0), "r"(b1));
}
__device__ __forceinline__ uint32_t pkbf2(__nv_bfloat16 a, __nv_bfloat16 b) {
    __nv_bfloat162 t = __halves2bfloat162(a, b);
    return *reinterpret_cast<uint32_t*>(&t);
}
// split float4 -> 4 hi bf16 (uint2) + 4 lo bf16 (uint2)
__device__ __forceinline__ void split4(float4 v, uint2& H, uint2& L) {
    __nv_bfloat16 h0 = __float2bfloat16_rn(v.x), h1 = __float2bfloat16_rn(v.y);
    __nv_bfloat16 h2 = __float2bfloat16_rn(v.z), h3 = __float2bfloat16_rn(v.w);
    __nv_bfloat16 l0 = __float2bfloat16_rn(v.x - __bfloat162float(h0));
    __nv_bfloat16 l1 = __float2bfloat16_rn(v.y - __bfloat162float(h1));
    __nv_bfloat16 l2 = __float2bfloat16_rn(v.z - __bfloat162float(h2));
    __nv_bfloat16 l3 = __float2bfloat16_rn(v.w - __bfloat162float(h3));
    H = make_uint2(pkbf2(h0, h1), pkbf2(h2, h3));
    L = make_uint2(pkbf2(l0, l1), pkbf2(l2, l3));
}

// ---------------- 1) embedding gather + bf16 split ----------------
__global__ __launch_bounds__(256) void gather_split(
    const int* __restrict__ tok, const float* __restrict__ emb,
    __nv_bfloat16* __restrict__ xhi, __nv_bfloat16* __restrict__ xlo)
{
    int id  = blockIdx.x * 256 + threadIdx.x;   // one float4 per thread
    int row = id >> 7;                          // 128 float4 per row
    int col = id & 127;
    int t   = tok[row];
    float4 v = reinterpret_cast<const float4*>(emb)[(size_t)t * 128 + col];
    uint2 H, L; split4(v, H, L);
    *reinterpret_cast<uint2*>(&xhi[(size_t)row * 512 + col * 4]) = H;
    *reinterpret_cast<uint2*>(&xlo[(size_t)row * 512 + col * 4]) = L;
}

// ---------------- 1b) weight split: 512x512 f32 -> bf16 hi/lo ----------------
__global__ __launch_bounds__(256) void wsplit(
    const float* __restrict__ w,
    __nv_bfloat16* __restrict__ whi, __nv_bfloat16* __restrict__ wlo)
{
    int i = blockIdx.x * 256 + threadIdx.x;     // 65536 float4
    float4 v = reinterpret_cast<const float4*>(w)[i];
    uint2 H, L; split4(v, H, L);
    *reinterpret_cast<uint2*>(&whi[(size_t)i * 4]) = H;
    *reinterpret_cast<uint2*>(&wlo[(size_t)i * 4]) = L;
}

// ---------------- 2) bf16-split tensor-core GEMM ----------------
// C[M,512] = A[M,512]·B[512,512]^T + bias1 + bias2  via  Ahi·Bhi + Ahi·Blo + Alo·Bhi
// CTA tile 128x256, 8 warps (2m x 4n) of 64x64; K chunks of 32, cp.async double buffer.
#define GM_THREADS 256
#define ST_A_LO    10240
#define ST_B_HI    20480
#define ST_B_OFF   20480   /* Blo - Bhi */
#define ST_SIZE    61440
#define GM_SMEM    (2*ST_SIZE + 1024)

__device__ __forceinline__ void gm_stage(
    int tid, int m0, int n0, int c, uint32_t sbase,
    const __nv_bfloat16* __restrict__ Ahi, const __nv_bfloat16* __restrict__ Alo,
    const __nv_bfloat16* __restrict__ Bhi, const __nv_bfloat16* __restrict__ Blo)
{
    const int k0 = c * 32;
    const uint32_t stg = sbase + (uint32_t)(c & 1) * ST_SIZE;
#pragma unroll
    for (int q = 0; q < 2; q++) {
        int i = tid + q * 256;
        int row = i >> 2, sg = i & 3;
        uint32_t d = stg + (uint32_t)row * 80 + sg * 16;
        size_t s = (size_t)(m0 + row) * 512 + k0 + sg * 8;
        cpasync16(d, Ahi + s);
        cpasync16(d + ST_A_LO, Alo + s);
    }
#pragma unroll
    for (int q = 0; q < 4; q++) {
        int i = tid + q * 256;
        int row = i >> 2, sg = i & 3;
        uint32_t d = stg + ST_B_HI + (uint32_t)row * 80 + sg * 16;
        size_t s = (size_t)(n0 + row) * 512 + k0 + sg * 8;
        cpasync16(d, Bhi + s);
        cpasync16(d + ST_B_OFF, Blo + s);
    }
    asm volatile("cp.async.commit_group;" ::: "memory");
}

__global__ __launch_bounds__(GM_THREADS) void sgemm_mma(
    const __nv_bfloat16* __restrict__ Ahi, const __nv_bfloat16* __restrict__ Alo,
    const __nv_bfloat16* __restrict__ Bhi, const __nv_bfloat16* __restrict__ Blo,
    const float* __restrict__ bias1, const float* __restrict__ bias2,
    float* __restrict__ C)
{
    extern __shared__ char smem[];
    const uint32_t sbase = smem_u32(smem);
    float* bsum = reinterpret_cast<float*>(smem + 2 * ST_SIZE);

    const int tid  = threadIdx.x;
    const int lane = tid & 31;
    const int wid  = tid >> 5;
    const int wm = wid & 1, wn = wid >> 1;
    const int g = lane >> 2, t = lane & 3;

    const int m0 = (blockIdx.x >> 1) * 128;
    const int n0 = (blockIdx.x & 1) * 256;

    bsum[tid] = bias1[n0 + tid] + bias2[n0 + tid];

    float acc[4][8][4];
#pragma unroll
    for (int mt = 0; mt < 4; mt++)
#pragma unroll
        for (int nt = 0; nt < 8; nt++)
#pragma unroll
            for (int r = 0; r < 4; r++) acc[mt][nt][r] = 0.f;

    gm_stage(tid, m0, n0, 0, sbase, Ahi, Alo, Bhi, Blo);

    for (int c = 0; c < 16; c++) {
        if (c + 1 < 16) {
            gm_stage(tid, m0, n0, c + 1, sbase, Ahi, Alo, Bhi, Blo);
            asm volatile("cp.async.wait_group 1;" ::: "memory");
        } else {
            asm volatile("cp.async.wait_group 0;" ::: "memory");
        }
        __syncthreads();

        const uint32_t stg = sbase + (uint32_t)(c & 1) * ST_SIZE;
#pragma unroll
        for (int kk = 0; kk < 2; kk++) {
            const uint32_t kb = kk * 32 + t * 4;
            uint32_t bh[8][2], bl[8][2];
#pragma unroll
            for (int nt = 0; nt < 8; nt++) {
                uint32_t ab = stg + ST_B_HI + (uint32_t)(wn * 64 + nt * 8 + g) * 80 + kb;
                bh[nt][0] = lds32(ab);
                bh[nt][1] = lds32(ab + 16);
                bl[nt][0] = lds32(ab + ST_B_OFF);
                bl[nt][1] = lds32(ab + ST_B_OFF + 16);
            }
#pragma unroll
            for (int mt = 0; mt < 4; mt++) {
                uint32_t ar = stg + (uint32_t)(wm * 64 + mt * 16 + g) * 80 + kb;
                uint32_t ah0 = lds32(ar),           ah1 = lds32(ar + 8 * 80);
                uint32_t ah2 = lds32(ar + 16),      ah3 = lds32(ar + 8 * 80 + 16);
                uint32_t al0 = lds32(ar + ST_A_LO),      al1 = lds32(ar + ST_A_LO + 8 * 80);
                uint32_t al2 = lds32(ar + ST_A_LO + 16), al3 = lds32(ar + ST_A_LO + 8 * 80 + 16);
#pragma unroll
                for (int nt = 0; nt < 8; nt++)
                    mma16816(acc[mt][nt], ah0, ah1, ah2, ah3, bh[nt][0], bh[nt][1]);
#pragma unroll
                for (int nt = 0; nt < 8; nt++)
                    mma16816(acc[mt][nt], ah0, ah1, ah2, ah3, bl[nt][0], bl[nt][1]);
#pragma unroll
                for (int nt = 0; nt < 8; nt++)
                    mma16816(acc[mt][nt], al0, al1, al2, al3, bh[nt][0], bh[nt][1]);
            }
        }
        __syncthreads();
    }

#pragma unroll
    for (int mt = 0; mt < 4; mt++) {
        int row = m0 + wm * 64 + mt * 16 + g;
#pragma unroll
        for (int nt = 0; nt < 8; nt++) {
            int cl = wn * 64 + nt * 8 + 2 * t;
            float b0 = bsum[cl], b1 = bsum[cl + 1];
            float2 v0 = make_float2(acc[mt][nt][0] + b0, acc[mt][nt][1] + b1);
            float2 v1 = make_float2(acc[mt][nt][2] + b0, acc[mt][nt][3] + b1);
            *reinterpret_cast<float2*>(&C[(size_t)row * 512 + n0 + cl]) = v0;
            *reinterpret_cast<float2*>(&C[(size_t)(row + 8) * 512 + n0 + cl]) = v1;
        }
    }
}

// ---------------- 3) recurrent layer v3: in-warp slices + shuffle reduce ----------------
// h_t = tanh(xp_t + W_hh @ h_{t-1}).  One CTA per (dir, batch), 512 threads.
// Lane layout: s = lane>>2 (k-slice, k0 = 32s), jq = lane&3; g = warp*4 + jq (0..63),
// outputs j = 4g..4g+3.  All 8 slices of an output live in ONE warp -> reduction is a
// 3-round shfl.xor butterfly (no P smem phase).  h double-buffered (+16B pad per 32
// floats for conflict-free slice-strided LDS.128) -> ONE __syncthreads per step.
// W: k-rows 0..23 of each slice in registers (96 regs), rows 24..31 in smem.
#define HPAD 288                               /* floats per h buffer (256 + 8*4 pad) */
#define RNN_SMEM_FLOATS (512*32 + 2*HPAD)
#define RNN_SMEM_BYTES  (RNN_SMEM_FLOATS * 4)

__global__ __launch_bounds__(512, 1) void rnn_layer(
    const float* __restrict__ xp,    // [B*T, 512]
    const float* __restrict__ Whh_l, // layer base: [2, 256, 256]
    float* __restrict__ xoutF,       // mode 1 target
    __nv_bfloat16* __restrict__ xoutH, __nv_bfloat16* __restrict__ xoutL, // mode 0
    int mode)
{
    extern __shared__ float sm[];
    float* Wsm  = sm;                 // 512 threads x 32 floats (lane-interleaved chunks)
    float* hbuf = sm + 512 * 32;      // 2 x HPAD padded h buffers

    const int tid  = threadIdx.x;
    const int w    = tid >> 5;
    const int lane = tid & 31;
    const int s    = lane >> 2;       // k-slice 0..7
    const int jq   = lane & 3;
    const int g    = w * 4 + jq;      // 0..63
    const int k0   = 32 * s;
    const int dir  = blockIdx.x >> 6;
    const int b    = blockIdx.x & 63;
    const float* W = Whh_l + (size_t)dir * HDIM * HDIM;   // [j][k] row-major

    // ---- thread-private smem W (lane-interleaved for conflict-free LDS.128):
    // chunk cc: jj = cc>>1, kb = 24 + 4*(cc&1)
    float4* WsmV = (float4*)Wsm;
#pragma unroll
    for (int cc = 0; cc < 8; cc++) {
        int jj = cc >> 1;
        int kb = 24 + 4 * (cc & 1);
        float4 wv = *(const float4*)&W[(size_t)(4*g + jj) * HDIM + k0 + kb];
        WsmV[(w * 8 + cc) * 32 + lane] = wv;
    }

    // ---- register W: k-pairs p=0..11 (krel 0..23) for 4 outputs
    unsigned long long wreg[12][4];
#pragma unroll
    for (int p = 0; p < 12; p++) {
#pragma unroll
        for (int jj = 0; jj < 4; jj++) {
            float2 wv = *(const float2*)&W[(size_t)(4*g + jj) * HDIM + k0 + 2*p];
            wreg[p][jj] = pack2(wv.x, wv.y);
        }
    }

    for (int i = tid; i < 2 * HPAD; i += 512) hbuf[i] = 0.f;

    const float* xpb = xp + (size_t)b * TLEN * EDIM + dir * HDIM;
    const size_t obase = (size_t)b * TLEN * EDIM + dir * HDIM;
    const int t0 = dir ? (TLEN - 1) : 0;
    const int dt = dir ? -1 : 1;

    // writer lanes: lane < 16; sw = lane>>2 (0..3 = jj it owns), j = w*16 + 4*jq + sw
    const bool writer = (lane < 16);
    const int jw   = w * 16 + 4 * jq + s;          // valid for writer lanes (s = sw)
    const int joff = jw + ((jw >> 5) << 2);        // padded h index

    float xp_cur = writer ? xpb[(size_t)t0 * EDIM + jw] : 0.f;

    const ulonglong2* wsv = (const ulonglong2*)Wsm + (w * 8) * 32 + lane;
    __syncthreads();

    int t = t0;
    for (int step = 0; step < TLEN; step++) {
        const float* hb = hbuf + (step & 1) * HPAD;
        float*       hw = hbuf + ((step & 1) ^ 1) * HPAD;
        const ulonglong2* hp2 = (const ulonglong2*)hb + 9 * s;   // padded slice base

        unsigned long long acc0 = 0ULL, acc1 = 0ULL, acc2 = 0ULL, acc3 = 0ULL;
#pragma unroll
        for (int c = 0; c < 3; c++) {               // krel 0..23 via 3 x (2 chunks)
            ulonglong2 hpa = hp2[2*c];
            ulonglong2 hpb = hp2[2*c+1];
            fma2(acc0, wreg[4*c+0][0], hpa.x);
            fma2(acc1, wreg[4*c+0][1], hpa.x);
            fma2(acc2, wreg[4*c+0][2], hpa.x);
            fma2(acc3, wreg[4*c+0][3], hpa.x);
            fma2(acc0, wreg[4*c+1][0], hpa.y);
            fma2(acc1, wreg[4*c+1][1], hpa.y);
            fma2(acc2, wreg[4*c+1][2], hpa.y);
            fma2(acc3, wreg[4*c+1][3], hpa.y);
            fma2(acc0, wreg[4*c+2][0], hpb.x);
            fma2(acc1, wreg[4*c+2][1], hpb.x);
            fma2(acc2, wreg[4*c+2][2], hpb.x);
            fma2(acc3, wreg[4*c+2][3], hpb.x);
            fma2(acc0, wreg[4*c+3][0], hpb.y);
            fma2(acc1, wreg[4*c+3][1], hpb.y);
            fma2(acc2, wreg[4*c+3][2], hpb.y);
            fma2(acc3, wreg[4*c+3][3], hpb.y);
        }
        {   // krel 24..31 from smem W
            ulonglong2 hp6 = hp2[6];
            ulonglong2 hp7 = hp2[7];
            ulonglong2 wv;
            wv = wsv[0*32]; fma2(acc0, wv.x, hp6.x); fma2(acc0, wv.y, hp6.y);
            wv = wsv[1*32]; fma2(acc0, wv.x, hp7.x); fma2(acc0, wv.y, hp7.y);
            wv = wsv[2*32]; fma2(acc1, wv.x, hp6.x); fma2(acc1, wv.y, hp6.y);
            wv = wsv[3*32]; fma2(acc1, wv.x, hp7.x); fma2(acc1, wv.y, hp7.y);
            wv = wsv[4*32]; fma2(acc2, wv.x, hp6.x); fma2(acc2, wv.y, hp6.y);
            wv = wsv[5*32]; fma2(acc2, wv.x, hp7.x); fma2(acc2, wv.y, hp7.y);
            wv = wsv[6*32]; fma2(acc3, wv.x, hp6.x); fma2(acc3, wv.y, hp6.y);
            wv = wsv[7*32]; fma2(acc3, wv.x, hp7.x); fma2(acc3, wv.y, hp7.y);
        }

        float2 u0 = unpack2(acc0), u1 = unpack2(acc1), u2 = unpack2(acc2), u3 = unpack2(acc3);
        float p0 = u0.x + u0.y;
        float p1 = u1.x + u1.y;
        float p2 = u2.x + u2.y;
        float p3 = u3.x + u3.y;

        // butterfly over slice bits (lane bits 2,3,4)
#pragma unroll
        for (int d = 4; d <= 16; d <<= 1) {
            p0 += __shfl_xor_sync(0xffffffffu, p0, d);
            p1 += __shfl_xor_sync(0xffffffffu, p1, d);
            p2 += __shfl_xor_sync(0xffffffffu, p2, d);
            p3 += __shfl_xor_sync(0xffffffffu, p3, d);
        }

        if (writer) {
            float total = (s == 0) ? p0 : (s == 1) ? p1 : (s == 2) ? p2 : p3;
            float pre = total + xp_cur;
            if (step + 1 < TLEN)
                xp_cur = xpb[(size_t)(t + dt) * EDIM + jw];
            float hv = tanhf(pre);
            hw[joff] = hv;
            if (mode) {
                xoutF[obase + (size_t)t * EDIM + jw] = fmaxf(hv, 0.f);
            } else {
                __nv_bfloat16 hh = __float2bfloat16_rn(hv);
                xoutH[obase + (size_t)t * EDIM + jw] = hh;
                xoutL[obase + (size_t)t * EDIM + jw] =
                    __float2bfloat16_rn(hv - __bfloat162float(hh));
            }
        }
        __syncthreads();
        t += dt;
    }
}

// ---------------- 4) head input projection ----------------
__global__ __launch_bounds__(256) void head_proj(
    const float* __restrict__ x,
    const float* __restrict__ wi, const float* __restrict__ wf, const float* __restrict__ wc,
    const float* __restrict__ bii, const float* __restrict__ bhi,
    const float* __restrict__ bif, const float* __restrict__ bhf,
    const float* __restrict__ bic, const float* __restrict__ bhc,
    float* __restrict__ hxp)
{
    __shared__ float xs[16 * 516];
    int tid = threadIdx.x;
    int row0 = blockIdx.x * 16;

    for (int i = tid; i < 16 * 128; i += 256) {
        int r = i >> 7, c = i & 127;
        float4 v = reinterpret_cast<const float4*>(x + (size_t)(row0 + r) * 512)[c];
        *(float4*)&xs[r * 516 + c * 4] = v;
    }
    __syncthreads();

    int r = tid >> 4, c = tid & 15;
    if (c < 13) {
        const float* w;
        float bias;
        if (c < 3)      { w = wi + (size_t)c * 512;        bias = bii[c]     + bhi[c];     }
        else if (c < 8) { w = wf + (size_t)(c - 3) * 512;  bias = bif[c - 3] + bhf[c - 3]; }
        else            { w = wc + (size_t)(c - 8) * 512;  bias = bic[c - 8] + bhc[c - 8]; }
        float sum = 0.f;
        const float* xr = &xs[r * 516];
#pragma unroll 8
        for (int k = 0; k < 512; k += 4) {
            float4 wv = *(const float4*)&w[k];
            sum += xr[k] * wv.x + xr[k+1] * wv.y + xr[k+2] * wv.z + xr[k+3] * wv.w;
        }
        hxp[(size_t)(row0 + r) * 16 + c] = sum + bias;
    }
}

// ---------------- 5) head recurrences ----------------
__global__ __launch_bounds__(256) void head_rnn(
    const float* __restrict__ hxp,
    const float* __restrict__ whi, const float* __restrict__ whf, const float* __restrict__ whc,
    float* __restrict__ out)
{
    int wg   = (blockIdx.x * 256 + threadIdx.x) >> 5;   // 0..191
    int lane = threadIdx.x & 31;
    if (wg >= BATCH * 3) return;
    int b = wg / 3, head = wg - 3 * b;

    int C    = (head == 0) ? 3 : 5;
    int coff = (head == 0) ? 0 : ((head == 1) ? 3 : 8);
    const float* whh = (head == 0) ? whi : ((head == 1) ? whf : whc);
    size_t ooff = (head == 0) ? 0
                : ((head == 1) ? (size_t)NROWS * 3 : (size_t)NROWS * 8);

    float wr[5] = {0.f, 0.f, 0.f, 0.f, 0.f};
    if (lane < C) {
#pragma unroll
        for (int j = 0; j < 5; j++) if (j < C) wr[j] = whh[lane * C + j];
    }

    int xoffs = (lane < C) ? (coff + lane) : 0;
    const float* xb = hxp + (size_t)b * TLEN * 16 + xoffs;
    float*       ob = out + ooff + (size_t)b * TLEN * C + lane;

    float hv = 0.f;
    float Acur[8], Anxt[8];
#pragma unroll
    for (int i = 0; i < 8; i++) Acur[i] = xb[(size_t)i * 16];

    for (int tb = 0; tb < TLEN; tb += 8) {
        bool more = (tb + 8) < TLEN;
#pragma unroll
        for (int i = 0; i < 8; i++)
            Anxt[i] = more ? xb[(size_t)(tb + 8 + i) * 16] : 0.f;

#pragma unroll
        for (int i = 0; i < 8; i++) {
            float sum = Acur[i];
#pragma unroll
            for (int j = 0; j < 5; j++) {
                float hj = __shfl_sync(0xffffffffu, hv, j);
                sum += wr[j] * hj;
            }
            hv = tanhf(sum);
            if (lane < C) ob[(size_t)(tb + i) * C] = hv;
        }
#pragma unroll
        for (int i = 0; i < 8; i++) Acur[i] = Anxt[i];
    }
}

// ---------------- launch ----------------
extern "C" void kernel_launch(void* const* d_in, const int* in_sizes, int n_in,
                              void* d_out, int out_size)
{
    const int*   tokens = (const int*)  d_in[0];
    const float* emb    = (const float*)d_in[1];
    const float* w_ih   = (const float*)d_in[2];   // [2,2,256,512]
    const float* w_hh   = (const float*)d_in[3];   // [2,2,256,256]
    const float* b_ih   = (const float*)d_in[4];   // [2,2,256]
    const float* b_hh   = (const float*)d_in[5];
    const float* iwi = (const float*)d_in[6];
    const float* iwh = (const float*)d_in[7];
    const float* ibi = (const float*)d_in[8];
    const float* ibh = (const float*)d_in[9];
    const float* fwi = (const float*)d_in[10];
    const float* fwh = (const float*)d_in[11];
    const float* fbi = (const float*)d_in[12];
    const float* fbh = (const float*)d_in[13];
    const float* cwi = (const float*)d_in[14];
    const float* cwh = (const float*)d_in[15];
    const float* cbi = (const float*)d_in[16];
    const float* cbh = (const float*)d_in[17];
    float* out = (float*)d_out;

    float *px, *pxp, *phxp;
    __nv_bfloat16 *pahi, *palo, *pbhi, *pblo;
    cudaGetSymbolAddress((void**)&px,   g_x);
    cudaGetSymbolAddress((void**)&pxp,  g_xp);
    cudaGetSymbolAddress((void**)&phxp, g_hxp);
    cudaGetSymbolAddress((void**)&pahi, g_ahi);
    cudaGetSymbolAddress((void**)&palo, g_alo);
    cudaGetSymbolAddress((void**)&pbhi, g_bhi);
    cudaGetSymbolAddress((void**)&pblo, g_blo);

    cudaFuncSetAttribute(rnn_layer, cudaFuncAttributeMaxDynamicSharedMemorySize, RNN_SMEM_BYTES);
    cudaFuncSetAttribute(sgemm_mma, cudaFuncAttributeMaxDynamicSharedMemorySize, GM_SMEM);

    // layer 0
    wsplit<<<256, 256>>>(w_ih, pbhi, pblo);
    gather_split<<<(NROWS * 128) / 256, 256>>>(tokens, emb, pahi, palo);
    sgemm_mma<<<1024, GM_THREADS, GM_SMEM>>>(pahi, palo, pbhi, pblo, b_ih, b_hh, pxp);
    rnn_layer<<<128, 512, RNN_SMEM_BYTES>>>(pxp, w_hh, nullptr, pahi, palo, 0);

    // layer 1 (relu fused into rnn output)
    wsplit<<<256, 256>>>(w_ih + (size_t)2 * HDIM * EDIM, pbhi, pblo);
    sgemm_mma<<<1024, GM_THREADS, GM_SMEM>>>(pahi, palo, pbhi, pblo,
                                             b_ih + 2 * HDIM, b_hh + 2 * HDIM, pxp);
    rnn_layer<<<128, 512, RNN_SMEM_BYTES>>>(pxp, w_hh + (size_t)2 * HDIM * HDIM,
                                            px, nullptr, nullptr, 1);

    // heads
    head_proj<<<NROWS / 16, 256>>>(px, iwi, fwi, cwi, ibi, ibh, fbi, fbh, cbi, cbh, phxp);
    head_rnn<<<24, 256>>>(phxp, iwh, fwh, cwh, out);
}

// round 10
// speedup vs baseline: 1.3120x; 1.3120x over previous
#include <cuda_runtime.h>
#include <cuda_bf16.h>
#include <cstdint>
#include <cstddef>

#define BATCH 64
#define TLEN  1024
#define EDIM  512
#define HDIM  256
#define NROWS (BATCH*TLEN)   /* 65536 */

// ---------------- scratch (device globals: allocation-free rule) ----------------
__device__ float          g_x  [(size_t)NROWS * EDIM];  // f32 activations (layer-1 out, head in)
__device__ float          g_xp [(size_t)NROWS * EDIM];  // input-projection results
__device__ float          g_hxp[(size_t)NROWS * 16];    // head projections (13 used)
__device__ __nv_bfloat16  g_ahi[(size_t)NROWS * EDIM];  // A hi (bf16 split of GEMM input)
__device__ __nv_bfloat16  g_alo[(size_t)NROWS * EDIM];  // A lo
__device__ __nv_bfloat16  g_bhi[(size_t)EDIM * EDIM];   // W hi (512x512)
__device__ __nv_bfloat16  g_blo[(size_t)EDIM * EDIM];   // W lo

// ---------------- packed f32x2 helpers ----------------
__device__ __forceinline__ unsigned long long pack2(float lo, float hi) {
    unsigned long long r;
    asm("mov.b64 %0, {%1,%2};" : "=l"(r) : "f"(lo), "f"(hi));
    return r;
}
__device__ __forceinline__ float2 unpack2(unsigned long long v) {
    float2 r;
    asm("mov.b64 {%0,%1}, %2;" : "=f"(r.x), "=f"(r.y) : "l"(v));
    return r;
}
__device__ __forceinline__ void fma2(unsigned long long &d, unsigned long long a, unsigned long long b) {
    asm("fma.rn.f32x2 %0, %1, %2, %0;" : "+l"(d) : "l"(a), "l"(b));
}

// ---------------- small helpers ----------------
__device__ __forceinline__ uint32_t smem_u32(const void* p) {
    uint32_t a;
    asm("{ .reg .u64 t; cvta.to.shared.u64 t, %1; cvt.u32.u64 %0, t; }" : "=r"(a) : "l"(p));
    return a;
}
__device__ __forceinline__ uint32_t lds32(uint32_t a) {
    uint32_t v; asm("ld.shared.b32 %0, [%1];" : "=r"(v) : "r"(a)); return v;
}
__device__ __forceinline__ void cpasync16(uint32_t dst, const void* src) {
    asm volatile("cp.async.cg.shared.global [%0], [%1], 16;" :: "r"(dst), "l"(src));
}
__device__ __forceinline__ void mma16816(float* d, uint32_t a0, uint32_t a1, uint32_t a2,
                                         uint32_t a3, uint32_t b0, uint32_t b1) {
    asm("mma.sync.aligned.m16n8k16.row.col.f32.bf16.bf16.f32 "
        "{%0,%1,%2,%3}, {%4,%5,%6,%7}, {%8,%9}, {%0,%1,%2,%3};"
        : "+f"(d[0]), "+f"(d[1]), "+f"(d[2]), "+f"(d[3])
        : "r"(a0), "r"(a1), "r"(a2), "r"(a3), "r"(b0), "r"(b1));
}
__device__ __forceinline__ uint32_t pkbf2(__nv_bfloat16 a, __nv_bfloat16 b) {
    __nv_bfloat162 t = __halves2bfloat162(a, b);
    return *reinterpret_cast<uint32_t*>(&t);
}
// split float4 -> 4 hi bf16 (uint2) + 4 lo bf16 (uint2)
__device__ __forceinline__ void split4(float4 v, uint2& H, uint2& L) {
    __nv_bfloat16 h0 = __float2bfloat16_rn(v.x), h1 = __float2bfloat16_rn(v.y);
    __nv_bfloat16 h2 = __float2bfloat16_rn(v.z), h3 = __float2bfloat16_rn(v.w);
    __nv_bfloat16 l0 = __float2bfloat16_rn(v.x - __bfloat162float(h0));
    __nv_bfloat16 l1 = __float2bfloat16_rn(v.y - __bfloat162float(h1));
    __nv_bfloat16 l2 = __float2bfloat16_rn(v.z - __bfloat162float(h2));
    __nv_bfloat16 l3 = __float2bfloat16_rn(v.w - __bfloat162float(h3));
    H = make_uint2(pkbf2(h0, h1), pkbf2(h2, h3));
    L = make_uint2(pkbf2(l0, l1), pkbf2(l2, l3));
}

// ---------------- 1) embedding gather + bf16 split ----------------
__global__ __launch_bounds__(256) void gather_split(
    const int* __restrict__ tok, const float* __restrict__ emb,
    __nv_bfloat16* __restrict__ xhi, __nv_bfloat16* __restrict__ xlo)
{
    int id  = blockIdx.x * 256 + threadIdx.x;   // one float4 per thread
    int row = id >> 7;                          // 128 float4 per row
    int col = id & 127;
    int t   = tok[row];
    float4 v = reinterpret_cast<const float4*>(emb)[(size_t)t * 128 + col];
    uint2 H, L; split4(v, H, L);
    *reinterpret_cast<uint2*>(&xhi[(size_t)row * 512 + col * 4]) = H;
    *reinterpret_cast<uint2*>(&xlo[(size_t)row * 512 + col * 4]) = L;
}

// ---------------- 1b) weight split: 512x512 f32 -> bf16 hi/lo ----------------
__global__ __launch_bounds__(256) void wsplit(
    const float* __restrict__ w,
    __nv_bfloat16* __restrict__ whi, __nv_bfloat16* __restrict__ wlo)
{
    int i = blockIdx.x * 256 + threadIdx.x;     // 65536 float4
    float4 v = reinterpret_cast<const float4*>(w)[i];
    uint2 H, L; split4(v, H, L);
    *reinterpret_cast<uint2*>(&whi[(size_t)i * 4]) = H;
    *reinterpret_cast<uint2*>(&wlo[(size_t)i * 4]) = L;
}

// ---------------- 2) bf16-split tensor-core GEMM ----------------
// C[M,512] = A[M,512]·B[512,512]^T + bias1 + bias2  via  Ahi·Bhi + Ahi·Blo + Alo·Bhi
// CTA tile 128x256, 8 warps (2m x 4n) of 64x64; K chunks of 32, cp.async double buffer.
#define GM_THREADS 256
#define ST_A_LO    10240
#define ST_B_HI    20480
#define ST_B_OFF   20480   /* Blo - Bhi */
#define ST_SIZE    61440
#define GM_SMEM    (2*ST_SIZE + 1024)

__device__ __forceinline__ void gm_stage(
    int tid, int m0, int n0, int c, uint32_t sbase,
    const __nv_bfloat16* __restrict__ Ahi, const __nv_bfloat16* __restrict__ Alo,
    const __nv_bfloat16* __restrict__ Bhi, const __nv_bfloat16* __restrict__ Blo)
{
    const int k0 = c * 32;
    const uint32_t stg = sbase + (uint32_t)(c & 1) * ST_SIZE;
#pragma unroll
    for (int q = 0; q < 2; q++) {
        int i = tid + q * 256;
        int row = i >> 2, sg = i & 3;
        uint32_t d = stg + (uint32_t)row * 80 + sg * 16;
        size_t s = (size_t)(m0 + row) * 512 + k0 + sg * 8;
        cpasync16(d, Ahi + s);
        cpasync16(d + ST_A_LO, Alo + s);
    }
#pragma unroll
    for (int q = 0; q < 4; q++) {
        int i = tid + q * 256;
        int row = i >> 2, sg = i & 3;
        uint32_t d = stg + ST_B_HI + (uint32_t)row * 80 + sg * 16;
        size_t s = (size_t)(n0 + row) * 512 + k0 + sg * 8;
        cpasync16(d, Bhi + s);
        cpasync16(d + ST_B_OFF, Blo + s);
    }
    asm volatile("cp.async.commit_group;" ::: "memory");
}

__global__ __launch_bounds__(GM_THREADS) void sgemm_mma(
    const __nv_bfloat16* __restrict__ Ahi, const __nv_bfloat16* __restrict__ Alo,
    const __nv_bfloat16* __restrict__ Bhi, const __nv_bfloat16* __restrict__ Blo,
    const float* __restrict__ bias1, const float* __restrict__ bias2,
    float* __restrict__ C)
{
    extern __shared__ char smem[];
    const uint32_t sbase = smem_u32(smem);
    float* bsum = reinterpret_cast<float*>(smem + 2 * ST_SIZE);

    const int tid  = threadIdx.x;
    const int lane = tid & 31;
    const int wid  = tid >> 5;
    const int wm = wid & 1, wn = wid >> 1;
    const int g = lane >> 2, t = lane & 3;

    const int m0 = (blockIdx.x >> 1) * 128;
    const int n0 = (blockIdx.x & 1) * 256;

    bsum[tid] = bias1[n0 + tid] + bias2[n0 + tid];

    float acc[4][8][4];
#pragma unroll
    for (int mt = 0; mt < 4; mt++)
#pragma unroll
        for (int nt = 0; nt < 8; nt++)
#pragma unroll
            for (int r = 0; r < 4; r++) acc[mt][nt][r] = 0.f;

    gm_stage(tid, m0, n0, 0, sbase, Ahi, Alo, Bhi, Blo);

    for (int c = 0; c < 16; c++) {
        if (c + 1 < 16) {
            gm_stage(tid, m0, n0, c + 1, sbase, Ahi, Alo, Bhi, Blo);
            asm volatile("cp.async.wait_group 1;" ::: "memory");
        } else {
            asm volatile("cp.async.wait_group 0;" ::: "memory");
        }
        __syncthreads();

        const uint32_t stg = sbase + (uint32_t)(c & 1) * ST_SIZE;
#pragma unroll
        for (int kk = 0; kk < 2; kk++) {
            const uint32_t kb = kk * 32 + t * 4;
            uint32_t bh[8][2], bl[8][2];
#pragma unroll
            for (int nt = 0; nt < 8; nt++) {
                uint32_t ab = stg + ST_B_HI + (uint32_t)(wn * 64 + nt * 8 + g) * 80 + kb;
                bh[nt][0] = lds32(ab);
                bh[nt][1] = lds32(ab + 16);
                bl[nt][0] = lds32(ab + ST_B_OFF);
                bl[nt][1] = lds32(ab + ST_B_OFF + 16);
            }
#pragma unroll
            for (int mt = 0; mt < 4; mt++) {
                uint32_t ar = stg + (uint32_t)(wm * 64 + mt * 16 + g) * 80 + kb;
                uint32_t ah0 = lds32(ar),           ah1 = lds32(ar + 8 * 80);
                uint32_t ah2 = lds32(ar + 16),      ah3 = lds32(ar + 8 * 80 + 16);
                uint32_t al0 = lds32(ar + ST_A_LO),      al1 = lds32(ar + ST_A_LO + 8 * 80);
                uint32_t al2 = lds32(ar + ST_A_LO + 16), al3 = lds32(ar + ST_A_LO + 8 * 80 + 16);
#pragma unroll
                for (int nt = 0; nt < 8; nt++)
                    mma16816(acc[mt][nt], ah0, ah1, ah2, ah3, bh[nt][0], bh[nt][1]);
#pragma unroll
                for (int nt = 0; nt < 8; nt++)
                    mma16816(acc[mt][nt], ah0, ah1, ah2, ah3, bl[nt][0], bl[nt][1]);
#pragma unroll
                for (int nt = 0; nt < 8; nt++)
                    mma16816(acc[mt][nt], al0, al1, al2, al3, bh[nt][0], bh[nt][1]);
            }
        }
        __syncthreads();
    }

#pragma unroll
    for (int mt = 0; mt < 4; mt++) {
        int row = m0 + wm * 64 + mt * 16 + g;
#pragma unroll
        for (int nt = 0; nt < 8; nt++) {
            int cl = wn * 64 + nt * 8 + 2 * t;
            float b0 = bsum[cl], b1 = bsum[cl + 1];
            float2 v0 = make_float2(acc[mt][nt][0] + b0, acc[mt][nt][1] + b1);
            float2 v1 = make_float2(acc[mt][nt][2] + b0, acc[mt][nt][3] + b1);
            *reinterpret_cast<float2*>(&C[(size_t)row * 512 + n0 + cl]) = v0;
            *reinterpret_cast<float2*>(&C[(size_t)(row + 8) * 512 + n0 + cl]) = v1;
        }
    }
}

// ---------------- 3) recurrent layer v4: 1 barrier, reduce-scatter, hoisted addrs ----
// h_t = tanh(xp_t + W_hh @ h_{t-1}).  One CTA per (dir, batch), 512 threads.
// Lane layout: s = lane>>2 (k-slice, k0 = 32s), jq = lane&3; g = w*4 + jq; 4 outputs
// j = 4g..4g+3 per thread as k-slice partials.  In-warp reduce is a 3-round
// REDUCE-SCATTER (4 shfl total): lane ends holding output j = 16w + 4*jq + 2*bit2 + bit3.
// h double-buffered with TWO precomputed pointer sets + 2x-unrolled loop (no per-step
// address math).  ONE __syncthreads per step.
// W: k-rows 0..23 in registers (96 f), rows 24..31 thread-private smem (+4f pad/32 for
// conflict-free slice-strided h LDS.128).
#define HPAD 288                               /* floats per h buffer (256 + 8*4 pad) */
#define RNN_SMEM_FLOATS (512*32 + 2*HPAD)
#define RNN_SMEM_BYTES  (RNN_SMEM_FLOATS * 4)

__global__ __launch_bounds__(512, 1) void rnn_layer(
    const float* __restrict__ xp,    // [B*T, 512]
    const float* __restrict__ Whh_l, // layer base: [2, 256, 256]
    float* __restrict__ xoutF,       // mode 1 target
    __nv_bfloat16* __restrict__ xoutH, __nv_bfloat16* __restrict__ xoutL, // mode 0
    int mode)
{
    extern __shared__ float sm[];
    float* Wsm = sm;                  // 512 threads x 32 floats (lane-interleaved chunks)
    float* hA  = sm + 512 * 32;       // h buffer A (initial state, read first)
    float* hB  = hA + HPAD;           // h buffer B

    const int tid  = threadIdx.x;
    const int w    = tid >> 5;
    const int lane = tid & 31;
    const int s    = lane >> 2;       // k-slice 0..7
    const int jq   = lane & 3;
    const int g    = w * 4 + jq;      // 0..63
    const int k0   = 32 * s;
    const int dir  = blockIdx.x >> 6;
    const int b    = blockIdx.x & 63;
    const float* W = Whh_l + (size_t)dir * HDIM * HDIM;   // [j][k] row-major

    // ---- thread-private smem W (lane-interleaved): chunk cc: jj = cc>>1, kb = 24+4*(cc&1)
    float4* WsmV = (float4*)Wsm;
#pragma unroll
    for (int cc = 0; cc < 8; cc++) {
        int jj = cc >> 1;
        int kb = 24 + 4 * (cc & 1);
        float4 wv = *(const float4*)&W[(size_t)(4*g + jj) * HDIM + k0 + kb];
        WsmV[(w * 8 + cc) * 32 + lane] = wv;
    }

    // ---- register W: k-pairs p=0..11 (krel 0..23) for 4 outputs
    unsigned long long wreg[12][4];
#pragma unroll
    for (int p = 0; p < 12; p++) {
#pragma unroll
        for (int jj = 0; jj < 4; jj++) {
            float2 wv = *(const float2*)&W[(size_t)(4*g + jj) * HDIM + k0 + 2*p];
            wreg[p][jj] = pack2(wv.x, wv.y);
        }
    }

    for (int i = tid; i < 2 * HPAD; i += 512) hA[i] = 0.f;

    const float* xpb = xp + (size_t)b * TLEN * EDIM + dir * HDIM;
    const size_t obase = (size_t)b * TLEN * EDIM + dir * HDIM;
    const int t0 = dir ? (TLEN - 1) : 0;
    const int dt = dir ? -1 : 1;

    const int  bit2   = (lane >> 2) & 1;
    const int  bit3   = (lane >> 3) & 1;
    const bool writer = (lane < 16);
    const int  jw     = 16 * w + 4 * jq + 2 * bit2 + bit3;   // output this lane ends with
    const int  joff   = jw + ((jw >> 5) << 2);               // padded h index

    // precomputed pointer sets (NO per-step address math)
    const ulonglong2* hsA = (const ulonglong2*)hA + 9 * s;
    const ulonglong2* hsB = (const ulonglong2*)hB + 9 * s;
    float* hwA = hA + joff;
    float* hwB = hB + joff;
    const ulonglong2* wsv = (const ulonglong2*)Wsm + (w * 8) * 32 + lane;

    float xp_cur = writer ? xpb[(size_t)t0 * EDIM + jw] : 0.f;
    __syncthreads();

    auto step_body = [&](const ulonglong2* HSRC, float* HDST, int tcur) {
        unsigned long long acc0 = 0ULL, acc1 = 0ULL, acc2 = 0ULL, acc3 = 0ULL;
#pragma unroll
        for (int c = 0; c < 3; c++) {               // krel 0..23 (register W)
            ulonglong2 hpa = HSRC[2*c];
            ulonglong2 hpb = HSRC[2*c+1];
            fma2(acc0, wreg[4*c+0][0], hpa.x);
            fma2(acc1, wreg[4*c+0][1], hpa.x);
            fma2(acc2, wreg[4*c+0][2], hpa.x);
            fma2(acc3, wreg[4*c+0][3], hpa.x);
            fma2(acc0, wreg[4*c+1][0], hpa.y);
            fma2(acc1, wreg[4*c+1][1], hpa.y);
            fma2(acc2, wreg[4*c+1][2], hpa.y);
            fma2(acc3, wreg[4*c+1][3], hpa.y);
            fma2(acc0, wreg[4*c+2][0], hpb.x);
            fma2(acc1, wreg[4*c+2][1], hpb.x);
            fma2(acc2, wreg[4*c+2][2], hpb.x);
            fma2(acc3, wreg[4*c+2][3], hpb.x);
            fma2(acc0, wreg[4*c+3][0], hpb.y);
            fma2(acc1, wreg[4*c+3][1], hpb.y);
            fma2(acc2, wreg[4*c+3][2], hpb.y);
            fma2(acc3, wreg[4*c+3][3], hpb.y);
        }
        {                                            // krel 24..31 (smem W)
            ulonglong2 hp6 = HSRC[6];
            ulonglong2 hp7 = HSRC[7];
            ulonglong2 wv;
            wv = wsv[0*32]; fma2(acc0, wv.x, hp6.x); fma2(acc0, wv.y, hp6.y);
            wv = wsv[1*32]; fma2(acc0, wv.x, hp7.x); fma2(acc0, wv.y, hp7.y);
            wv = wsv[2*32]; fma2(acc1, wv.x, hp6.x); fma2(acc1, wv.y, hp6.y);
            wv = wsv[3*32]; fma2(acc1, wv.x, hp7.x); fma2(acc1, wv.y, hp7.y);
            wv = wsv[4*32]; fma2(acc2, wv.x, hp6.x); fma2(acc2, wv.y, hp6.y);
            wv = wsv[5*32]; fma2(acc2, wv.x, hp7.x); fma2(acc2, wv.y, hp7.y);
            wv = wsv[6*32]; fma2(acc3, wv.x, hp6.x); fma2(acc3, wv.y, hp6.y);
            wv = wsv[7*32]; fma2(acc3, wv.x, hp7.x); fma2(acc3, wv.y, hp7.y);
        }

        float2 u0 = unpack2(acc0), u1 = unpack2(acc1), u2 = unpack2(acc2), u3 = unpack2(acc3);
        float p0 = u0.x + u0.y;
        float p1 = u1.x + u1.y;
        float p2 = u2.x + u2.y;
        float p3 = u3.x + u3.y;

        // reduce-scatter over slice bits (4 shfl total)
        float r0 = __shfl_xor_sync(0xffffffffu, bit2 ? p0 : p2, 4);
        float r1 = __shfl_xor_sync(0xffffffffu, bit2 ? p1 : p3, 4);
        if (!bit2) { p0 += r0; p1 += r1; } else { p2 += r0; p3 += r1; }
        float va = bit2 ? p2 : p0;
        float vb = bit2 ? p3 : p1;
        float r2 = __shfl_xor_sync(0xffffffffu, bit3 ? va : vb, 8);
        float v  = bit3 ? (vb + r2) : (va + r2);
        v += __shfl_xor_sync(0xffffffffu, v, 16);

        if (writer) {
            float pre = v + xp_cur;
            int tn = tcur + dt;
            tn = tn < 0 ? 0 : (tn >= TLEN ? TLEN - 1 : tn);
            xp_cur = xpb[(size_t)tn * EDIM + jw];    // next step's xp (redundant at end)
            float hv = tanhf(pre);
            *HDST = hv;
            if (mode) {
                xoutF[obase + (size_t)tcur * EDIM + jw] = fmaxf(hv, 0.f);
            } else {
                __nv_bfloat16 hh = __float2bfloat16_rn(hv);
                xoutH[obase + (size_t)tcur * EDIM + jw] = hh;
                xoutL[obase + (size_t)tcur * EDIM + jw] =
                    __float2bfloat16_rn(hv - __bfloat162float(hh));
            }
        }
        __syncthreads();
    };

    int t = t0;
    for (int it = 0; it < TLEN / 2; it++) {
        step_body(hsA, hwB, t); t += dt;    // read A, write B
        step_body(hsB, hwA, t); t += dt;    // read B, write A
    }
}

// ---------------- 4) head input projection ----------------
__global__ __launch_bounds__(256) void head_proj(
    const float* __restrict__ x,
    const float* __restrict__ wi, const float* __restrict__ wf, const float* __restrict__ wc,
    const float* __restrict__ bii, const float* __restrict__ bhi,
    const float* __restrict__ bif, const float* __restrict__ bhf,
    const float* __restrict__ bic, const float* __restrict__ bhc,
    float* __restrict__ hxp)
{
    __shared__ float xs[16 * 516];
    int tid = threadIdx.x;
    int row0 = blockIdx.x * 16;

    for (int i = tid; i < 16 * 128; i += 256) {
        int r = i >> 7, c = i & 127;
        float4 v = reinterpret_cast<const float4*>(x + (size_t)(row0 + r) * 512)[c];
        *(float4*)&xs[r * 516 + c * 4] = v;
    }
    __syncthreads();

    int r = tid >> 4, c = tid & 15;
    if (c < 13) {
        const float* w;
        float bias;
        if (c < 3)      { w = wi + (size_t)c * 512;        bias = bii[c]     + bhi[c];     }
        else if (c < 8) { w = wf + (size_t)(c - 3) * 512;  bias = bif[c - 3] + bhf[c - 3]; }
        else            { w = wc + (size_t)(c - 8) * 512;  bias = bic[c - 8] + bhc[c - 8]; }
        float sum = 0.f;
        const float* xr = &xs[r * 516];
#pragma unroll 8
        for (int k = 0; k < 512; k += 4) {
            float4 wv = *(const float4*)&w[k];
            sum += xr[k] * wv.x + xr[k+1] * wv.y + xr[k+2] * wv.z + xr[k+3] * wv.w;
        }
        hxp[(size_t)(row0 + r) * 16 + c] = sum + bias;
    }
}

// ---------------- 5) head recurrences ----------------
__global__ __launch_bounds__(256) void head_rnn(
    const float* __restrict__ hxp,
    const float* __restrict__ whi, const float* __restrict__ whf, const float* __restrict__ whc,
    float* __restrict__ out)
{
    int wg   = (blockIdx.x * 256 + threadIdx.x) >> 5;   // 0..191
    int lane = threadIdx.x & 31;
    if (wg >= BATCH * 3) return;
    int b = wg / 3, head = wg - 3 * b;

    int C    = (head == 0) ? 3 : 5;
    int coff = (head == 0) ? 0 : ((head == 1) ? 3 : 8);
    const float* whh = (head == 0) ? whi : ((head == 1) ? whf : whc);
    size_t ooff = (head == 0) ? 0
                : ((head == 1) ? (size_t)NROWS * 3 : (size_t)NROWS * 8);

    float wr[5] = {0.f, 0.f, 0.f, 0.f, 0.f};
    if (lane < C) {
#pragma unroll
        for (int j = 0; j < 5; j++) if (j < C) wr[j] = whh[lane * C + j];
    }

    int xoffs = (lane < C) ? (coff + lane) : 0;
    const float* xb = hxp + (size_t)b * TLEN * 16 + xoffs;
    float*       ob = out + ooff + (size_t)b * TLEN * C + lane;

    float hv = 0.f;
    float Acur[8], Anxt[8];
#pragma unroll
    for (int i = 0; i < 8; i++) Acur[i] = xb[(size_t)i * 16];

    for (int tb = 0; tb < TLEN; tb += 8) {
        bool more = (tb + 8) < TLEN;
#pragma unroll
        for (int i = 0; i < 8; i++)
            Anxt[i] = more ? xb[(size_t)(tb + 8 + i) * 16] : 0.f;

#pragma unroll
        for (int i = 0; i < 8; i++) {
            float sum = Acur[i];
#pragma unroll
            for (int j = 0; j < 5; j++) {
                float hj = __shfl_sync(0xffffffffu, hv, j);
                sum += wr[j] * hj;
            }
            hv = tanhf(sum);
            if (lane < C) ob[(size_t)(tb + i) * C] = hv;
        }
#pragma unroll
        for (int i = 0; i < 8; i++) Acur[i] = Anxt[i];
    }
}

// ---------------- launch ----------------
extern "C" void kernel_launch(void* const* d_in, const int* in_sizes, int n_in,
                              void* d_out, int out_size)
{
    const int*   tokens = (const int*)  d_in[0];
    const float* emb    = (const float*)d_in[1];
    const float* w_ih   = (const float*)d_in[2];   // [2,2,256,512]
    const float* w_hh   = (const float*)d_in[3];   // [2,2,256,256]
    const float* b_ih   = (const float*)d_in[4];   // [2,2,256]
    const float* b_hh   = (const float*)d_in[5];
    const float* iwi = (const float*)d_in[6];
    const float* iwh = (const float*)d_in[7];
    const float* ibi = (const float*)d_in[8];
    const float* ibh = (const float*)d_in[9];
    const float* fwi = (const float*)d_in[10];
    const float* fwh = (const float*)d_in[11];
    const float* fbi = (const float*)d_in[12];
    const float* fbh = (const float*)d_in[13];
    const float* cwi = (const float*)d_in[14];
    const float* cwh = (const float*)d_in[15];
    const float* cbi = (const float*)d_in[16];
    const float* cbh = (const float*)d_in[17];
    float* out = (float*)d_out;

    float *px, *pxp, *phxp;
    __nv_bfloat16 *pahi, *palo, *pbhi, *pblo;
    cudaGetSymbolAddress((void**)&px,   g_x);
    cudaGetSymbolAddress((void**)&pxp,  g_xp);
    cudaGetSymbolAddress((void**)&phxp, g_hxp);
    cudaGetSymbolAddress((void**)&pahi, g_ahi);
    cudaGetSymbolAddress((void**)&palo, g_alo);
    cudaGetSymbolAddress((void**)&pbhi, g_bhi);
    cudaGetSymbolAddress((void**)&pblo, g_blo);

    cudaFuncSetAttribute(rnn_layer, cudaFuncAttributeMaxDynamicSharedMemorySize, RNN_SMEM_BYTES);
    cudaFuncSetAttribute(sgemm_mma, cudaFuncAttributeMaxDynamicSharedMemorySize, GM_SMEM);

    // layer 0
    wsplit<<<256, 256>>>(w_ih, pbhi, pblo);
    gather_split<<<(NROWS * 128) / 256, 256>>>(tokens, emb, pahi, palo);
    sgemm_mma<<<1024, GM_THREADS, GM_SMEM>>>(pahi, palo, pbhi, pblo, b_ih, b_hh, pxp);
    rnn_layer<<<128, 512, RNN_SMEM_BYTES>>>(pxp, w_hh, nullptr, pahi, palo, 0);

    // layer 1 (relu fused into rnn output)
    wsplit<<<256, 256>>>(w_ih + (size_t)2 * HDIM * EDIM, pbhi, pblo);
    sgemm_mma<<<1024, GM_THREADS, GM_SMEM>>>(pahi, palo, pbhi, pblo,
                                             b_ih + 2 * HDIM, b_hh + 2 * HDIM, pxp);
    rnn_layer<<<128, 512, RNN_SMEM_BYTES>>>(pxp, w_hh + (size_t)2 * HDIM * HDIM,
                                            px, nullptr, nullptr, 1);

    // heads
    head_proj<<<NROWS / 16, 256>>>(px, iwi, fwi, cwi, ibi, ibh, fbi, fbh, cbi, cbh, phxp);
    head_rnn<<<24, 256>>>(phxp, iwh, fwh, cwh, out);
}

// round 17
// speedup vs baseline: 1.3520x; 1.0305x over previous
#include <cuda_runtime.h>
#include <cuda_bf16.h>
#include <cstdint>
#include <cstddef>

#define BATCH 64
#define TLEN  1024
#define EDIM  512
#define HDIM  256
#define NROWS (BATCH*TLEN)   /* 65536 */

// ---------------- scratch (device globals: allocation-free rule) ----------------
__device__ float          g_x  [(size_t)NROWS * EDIM];  // f32 activations (layer-1 out, head in)
__device__ float          g_xp [(size_t)NROWS * EDIM];  // input-projection results
__device__ float          g_hxp[(size_t)NROWS * 16];    // head projections (13 used)
__device__ __nv_bfloat16  g_ahi[(size_t)NROWS * EDIM];  // A hi (bf16 split of GEMM input)
__device__ __nv_bfloat16  g_alo[(size_t)NROWS * EDIM];  // A lo
__device__ __nv_bfloat16  g_bhi[(size_t)EDIM * EDIM];   // W hi (512x512)
__device__ __nv_bfloat16  g_blo[(size_t)EDIM * EDIM];   // W lo

// ---------------- packed f32x2 helpers ----------------
__device__ __forceinline__ unsigned long long pack2(float lo, float hi) {
    unsigned long long r;
    asm("mov.b64 %0, {%1,%2};" : "=l"(r) : "f"(lo), "f"(hi));
    return r;
}
__device__ __forceinline__ float2 unpack2(unsigned long long v) {
    float2 r;
    asm("mov.b64 {%0,%1}, %2;" : "=f"(r.x), "=f"(r.y) : "l"(v));
    return r;
}
__device__ __forceinline__ void fma2(unsigned long long &d, unsigned long long a, unsigned long long b) {
    asm("fma.rn.f32x2 %0, %1, %2, %0;" : "+l"(d) : "l"(a), "l"(b));
}

// ---------------- small helpers ----------------
__device__ __forceinline__ uint32_t smem_u32(const void* p) {
    uint32_t a;
    asm("{ .reg .u64 t; cvta.to.shared.u64 t, %1; cvt.u32.u64 %0, t; }" : "=r"(a) : "l"(p));
    return a;
}
__device__ __forceinline__ uint32_t lds32(uint32_t a) {
    uint32_t v; asm("ld.shared.b32 %0, [%1];" : "=r"(v) : "r"(a)); return v;
}
__device__ __forceinline__ void cpasync16(uint32_t dst, const void* src) {
    asm volatile("cp.async.cg.shared.global [%0], [%1], 16;" :: "r"(dst), "l"(src));
}
__device__ __forceinline__ void mma16816(float* d, uint32_t a0, uint32_t a1, uint32_t a2,
                                         uint32_t a3, uint32_t b0, uint32_t b1) {
    asm("mma.sync.aligned.m16n8k16.row.col.f32.bf16.bf16.f32 "
        "{%0,%1,%2,%3}, {%4,%5,%6,%7}, {%8,%9}, {%0,%1,%2,%3};"
        : "+f"(d[0]), "+f"(d[1]), "+f"(d[2]), "+f"(d[3])
        : "r"(a0), "r"(a1), "r"(a2), "r"(a3), "r"(b0), "r"(b1));
}
__device__ __forceinline__ uint32_t pkbf2(__nv_bfloat16 a, __nv_bfloat16 b) {
    __nv_bfloat162 t = __halves2bfloat162(a, b);
    return *reinterpret_cast<uint32_t*>(&t);
}
// split float4 -> 4 hi bf16 (uint2) + 4 lo bf16 (uint2)
__device__ __forceinline__ void split4(float4 v, uint2& H, uint2& L) {
    __nv_bfloat16 h0 = __float2bfloat16_rn(v.x), h1 = __float2bfloat16_rn(v.y);
    __nv_bfloat16 h2 = __float2bfloat16_rn(v.z), h3 = __float2bfloat16_rn(v.w);
    __nv_bfloat16 l0 = __float2bfloat16_rn(v.x - __bfloat162float(h0));
    __nv_bfloat16 l1 = __float2bfloat16_rn(v.y - __bfloat162float(h1));
    __nv_bfloat16 l2 = __float2bfloat16_rn(v.z - __bfloat162float(h2));
    __nv_bfloat16 l3 = __float2bfloat16_rn(v.w - __bfloat162float(h3));
    H = make_uint2(pkbf2(h0, h1), pkbf2(h2, h3));
    L = make_uint2(pkbf2(l0, l1), pkbf2(l2, l3));
}

// ---------------- 1) embedding gather + bf16 split ----------------
__global__ __launch_bounds__(256) void gather_split(
    const int* __restrict__ tok, const float* __restrict__ emb,
    __nv_bfloat16* __restrict__ xhi, __nv_bfloat16* __restrict__ xlo)
{
    int id  = blockIdx.x * 256 + threadIdx.x;   // one float4 per thread
    int row = id >> 7;                          // 128 float4 per row
    int col = id & 127;
    int t   = tok[row];
    float4 v = reinterpret_cast<const float4*>(emb)[(size_t)t * 128 + col];
    uint2 H, L; split4(v, H, L);
    *reinterpret_cast<uint2*>(&xhi[(size_t)row * 512 + col * 4]) = H;
    *reinterpret_cast<uint2*>(&xlo[(size_t)row * 512 + col * 4]) = L;
}

// ---------------- 1b) weight split: 512x512 f32 -> bf16 hi/lo ----------------
__global__ __launch_bounds__(256) void wsplit(
    const float* __restrict__ w,
    __nv_bfloat16* __restrict__ whi, __nv_bfloat16* __restrict__ wlo)
{
    int i = blockIdx.x * 256 + threadIdx.x;     // 65536 float4
    float4 v = reinterpret_cast<const float4*>(w)[i];
    uint2 H, L; split4(v, H, L);
    *reinterpret_cast<uint2*>(&whi[(size_t)i * 4]) = H;
    *reinterpret_cast<uint2*>(&wlo[(size_t)i * 4]) = L;
}

// ---------------- 2) bf16-split tensor-core GEMM ----------------
// C[M,512] = A[M,512]·B[512,512]^T + bias1 + bias2  via  Ahi·Bhi + Ahi·Blo + Alo·Bhi
// CTA tile 128x256, 8 warps (2m x 4n) of 64x64; K chunks of 32, cp.async double buffer.
#define GM_THREADS 256
#define ST_A_LO    10240
#define ST_B_HI    20480
#define ST_B_OFF   20480   /* Blo - Bhi */
#define ST_SIZE    61440
#define GM_SMEM    (2*ST_SIZE + 1024)

__device__ __forceinline__ void gm_stage(
    int tid, int m0, int n0, int c, uint32_t sbase,
    const __nv_bfloat16* __restrict__ Ahi, const __nv_bfloat16* __restrict__ Alo,
    const __nv_bfloat16* __restrict__ Bhi, const __nv_bfloat16* __restrict__ Blo)
{
    const int k0 = c * 32;
    const uint32_t stg = sbase + (uint32_t)(c & 1) * ST_SIZE;
#pragma unroll
    for (int q = 0; q < 2; q++) {
        int i = tid + q * 256;
        int row = i >> 2, sg = i & 3;
        uint32_t d = stg + (uint32_t)row * 80 + sg * 16;
        size_t s = (size_t)(m0 + row) * 512 + k0 + sg * 8;
        cpasync16(d, Ahi + s);
        cpasync16(d + ST_A_LO, Alo + s);
    }
#pragma unroll
    for (int q = 0; q < 4; q++) {
        int i = tid + q * 256;
        int row = i >> 2, sg = i & 3;
        uint32_t d = stg + ST_B_HI + (uint32_t)row * 80 + sg * 16;
        size_t s = (size_t)(n0 + row) * 512 + k0 + sg * 8;
        cpasync16(d, Bhi + s);
        cpasync16(d + ST_B_OFF, Blo + s);
    }
    asm volatile("cp.async.commit_group;" ::: "memory");
}

__global__ __launch_bounds__(GM_THREADS) void sgemm_mma(
    const __nv_bfloat16* __restrict__ Ahi, const __nv_bfloat16* __restrict__ Alo,
    const __nv_bfloat16* __restrict__ Bhi, const __nv_bfloat16* __restrict__ Blo,
    const float* __restrict__ bias1, const float* __restrict__ bias2,
    float* __restrict__ C)
{
    extern __shared__ char smem[];
    const uint32_t sbase = smem_u32(smem);
    float* bsum = reinterpret_cast<float*>(smem + 2 * ST_SIZE);

    const int tid  = threadIdx.x;
    const int lane = tid & 31;
    const int wid  = tid >> 5;
    const int wm = wid & 1, wn = wid >> 1;
    const int g = lane >> 2, t = lane & 3;

    const int m0 = (blockIdx.x >> 1) * 128;
    const int n0 = (blockIdx.x & 1) * 256;

    bsum[tid] = bias1[n0 + tid] + bias2[n0 + tid];

    float acc[4][8][4];
#pragma unroll
    for (int mt = 0; mt < 4; mt++)
#pragma unroll
        for (int nt = 0; nt < 8; nt++)
#pragma unroll
            for (int r = 0; r < 4; r++) acc[mt][nt][r] = 0.f;

    gm_stage(tid, m0, n0, 0, sbase, Ahi, Alo, Bhi, Blo);

    for (int c = 0; c < 16; c++) {
        if (c + 1 < 16) {
            gm_stage(tid, m0, n0, c + 1, sbase, Ahi, Alo, Bhi, Blo);
            asm volatile("cp.async.wait_group 1;" ::: "memory");
        } else {
            asm volatile("cp.async.wait_group 0;" ::: "memory");
        }
        __syncthreads();

        const uint32_t stg = sbase + (uint32_t)(c & 1) * ST_SIZE;
#pragma unroll
        for (int kk = 0; kk < 2; kk++) {
            const uint32_t kb = kk * 32 + t * 4;
            uint32_t bh[8][2], bl[8][2];
#pragma unroll
            for (int nt = 0; nt < 8; nt++) {
                uint32_t ab = stg + ST_B_HI + (uint32_t)(wn * 64 + nt * 8 + g) * 80 + kb;
                bh[nt][0] = lds32(ab);
                bh[nt][1] = lds32(ab + 16);
                bl[nt][0] = lds32(ab + ST_B_OFF);
                bl[nt][1] = lds32(ab + ST_B_OFF + 16);
            }
#pragma unroll
            for (int mt = 0; mt < 4; mt++) {
                uint32_t ar = stg + (uint32_t)(wm * 64 + mt * 16 + g) * 80 + kb;
                uint32_t ah0 = lds32(ar),           ah1 = lds32(ar + 8 * 80);
                uint32_t ah2 = lds32(ar + 16),      ah3 = lds32(ar + 8 * 80 + 16);
                uint32_t al0 = lds32(ar + ST_A_LO),      al1 = lds32(ar + ST_A_LO + 8 * 80);
                uint32_t al2 = lds32(ar + ST_A_LO + 16), al3 = lds32(ar + ST_A_LO + 8 * 80 + 16);
#pragma unroll
                for (int nt = 0; nt < 8; nt++)
                    mma16816(acc[mt][nt], ah0, ah1, ah2, ah3, bh[nt][0], bh[nt][1]);
#pragma unroll
                for (int nt = 0; nt < 8; nt++)
                    mma16816(acc[mt][nt], ah0, ah1, ah2, ah3, bl[nt][0], bl[nt][1]);
#pragma unroll
                for (int nt = 0; nt < 8; nt++)
                    mma16816(acc[mt][nt], al0, al1, al2, al3, bh[nt][0], bh[nt][1]);
            }
        }
        __syncthreads();
    }

#pragma unroll
    for (int mt = 0; mt < 4; mt++) {
        int row = m0 + wm * 64 + mt * 16 + g;
#pragma unroll
        for (int nt = 0; nt < 8; nt++) {
            int cl = wn * 64 + nt * 8 + 2 * t;
            float b0 = bsum[cl], b1 = bsum[cl + 1];
            float2 v0 = make_float2(acc[mt][nt][0] + b0, acc[mt][nt][1] + b1);
            float2 v1 = make_float2(acc[mt][nt][2] + b0, acc[mt][nt][3] + b1);
            *reinterpret_cast<float2*>(&C[(size_t)row * 512 + n0 + cl]) = v0;
            *reinterpret_cast<float2*>(&C[(size_t)(row + 8) * 512 + n0 + cl]) = v1;
        }
    }
}

// ---------------- 3) recurrent layer v5: v4 + spill elimination ----------------
// h_t = tanh(xp_t + W_hh @ h_{t-1}).  One CTA per (dir, batch), 512 threads.
// Same 1-barrier reduce-scatter structure as v4 (measured WIN at R10), with register
// pressure reduced below the 128-reg cap (R10 ncu showed regs=128 + ~2x the expected
// issue slots -> spill traffic):
//   - wreg shrunk 12 -> 10 k-pairs (krel 0..19, 80 regs); krel 20..31 (12 rows) now in
//     thread-private smem (48 floats/thread, 96KB -> 12 LDS.128/step, +4 vs v4).
//   - mode is a template parameter (no runtime branch, no dead pointer registers).
#define HPAD 288                               /* floats per h buffer (256 + 8*4 pad) */
#define RNN_SMEM_FLOATS (512*48 + 2*HPAD)
#define RNN_SMEM_BYTES  (RNN_SMEM_FLOATS * 4)

template <int MODE>
__global__ __launch_bounds__(512, 1) void rnn_layer_t(
    const float* __restrict__ xp,    // [B*T, 512]
    const float* __restrict__ Whh_l, // layer base: [2, 256, 256]
    float* __restrict__ xoutF,       // MODE 1 target
    __nv_bfloat16* __restrict__ xoutH, __nv_bfloat16* __restrict__ xoutL) // MODE 0
{
    extern __shared__ float sm[];
    float* Wsm = sm;                  // 512 threads x 48 floats (lane-interleaved chunks)
    float* hA  = sm + 512 * 48;       // h buffer A (initial state, read first)
    float* hB  = hA + HPAD;           // h buffer B

    const int tid  = threadIdx.x;
    const int w    = tid >> 5;
    const int lane = tid & 31;
    const int s    = lane >> 2;       // k-slice 0..7
    const int jq   = lane & 3;
    const int g    = w * 4 + jq;      // 0..63
    const int k0   = 32 * s;
    const int dir  = blockIdx.x >> 6;
    const int b    = blockIdx.x & 63;
    const float* W = Whh_l + (size_t)dir * HDIM * HDIM;   // [j][k] row-major

    // ---- thread-private smem W: 12 chunks; chunk cc = jj*3 + q covers output jj,
    //      krel rows 20+4q .. 23+4q (as 2 k-pairs in one float4)
    float4* WsmV = (float4*)Wsm;
#pragma unroll
    for (int cc = 0; cc < 12; cc++) {
        int jj = cc / 3;
        int q  = cc % 3;
        float4 wv = *(const float4*)&W[(size_t)(4*g + jj) * HDIM + k0 + 20 + 4*q];
        WsmV[(w * 12 + cc) * 32 + lane] = wv;
    }

    // ---- register W: k-pairs p=0..9 (krel 0..19) for 4 outputs (80 regs)
    unsigned long long wreg[10][4];
#pragma unroll
    for (int p = 0; p < 10; p++) {
#pragma unroll
        for (int jj = 0; jj < 4; jj++) {
            float2 wv = *(const float2*)&W[(size_t)(4*g + jj) * HDIM + k0 + 2*p];
            wreg[p][jj] = pack2(wv.x, wv.y);
        }
    }

    for (int i = tid; i < 2 * HPAD; i += 512) hA[i] = 0.f;

    const float* xpb = xp + (size_t)b * TLEN * EDIM + dir * HDIM;
    const size_t obase = (size_t)b * TLEN * EDIM + dir * HDIM;
    const int t0 = dir ? (TLEN - 1) : 0;
    const int dt = dir ? -1 : 1;

    const int  bit2   = (lane >> 2) & 1;
    const int  bit3   = (lane >> 3) & 1;
    const bool writer = (lane < 16);
    const int  jw     = 16 * w + 4 * jq + 2 * bit2 + bit3;   // output this lane ends with
    const int  joff   = jw + ((jw >> 5) << 2);               // padded h index

    // precomputed pointer sets (NO per-step address math)
    const ulonglong2* hsA = (const ulonglong2*)hA + 9 * s;
    const ulonglong2* hsB = (const ulonglong2*)hB + 9 * s;
    float* hwA = hA + joff;
    float* hwB = hB + joff;
    const ulonglong2* wsv = (const ulonglong2*)Wsm + (w * 12) * 32 + lane;

    float xp_cur = writer ? xpb[(size_t)t0 * EDIM + jw] : 0.f;
    __syncthreads();

    auto step_body = [&](const ulonglong2* HSRC, float* HDST, int tcur) {
        unsigned long long acc0 = 0ULL, acc1 = 0ULL, acc2 = 0ULL, acc3 = 0ULL;
#pragma unroll
        for (int c = 0; c < 5; c++) {               // krel 0..19 (register W)
            ulonglong2 hp = HSRC[c];
            fma2(acc0, wreg[2*c+0][0], hp.x);
            fma2(acc1, wreg[2*c+0][1], hp.x);
            fma2(acc2, wreg[2*c+0][2], hp.x);
            fma2(acc3, wreg[2*c+0][3], hp.x);
            fma2(acc0, wreg[2*c+1][0], hp.y);
            fma2(acc1, wreg[2*c+1][1], hp.y);
            fma2(acc2, wreg[2*c+1][2], hp.y);
            fma2(acc3, wreg[2*c+1][3], hp.y);
        }
#pragma unroll
        for (int q = 0; q < 3; q++) {               // krel 20..31 (smem W)
            ulonglong2 hp = HSRC[5 + q];
            ulonglong2 wv0 = wsv[(0*3 + q) * 32];
            ulonglong2 wv1 = wsv[(1*3 + q) * 32];
            ulonglong2 wv2 = wsv[(2*3 + q) * 32];
            ulonglong2 wv3 = wsv[(3*3 + q) * 32];
            fma2(acc0, wv0.x, hp.x); fma2(acc0, wv0.y, hp.y);
            fma2(acc1, wv1.x, hp.x); fma2(acc1, wv1.y, hp.y);
            fma2(acc2, wv2.x, hp.x); fma2(acc2, wv2.y, hp.y);
            fma2(acc3, wv3.x, hp.x); fma2(acc3, wv3.y, hp.y);
        }

        float2 u0 = unpack2(acc0), u1 = unpack2(acc1), u2 = unpack2(acc2), u3 = unpack2(acc3);
        float p0 = u0.x + u0.y;
        float p1 = u1.x + u1.y;
        float p2 = u2.x + u2.y;
        float p3 = u3.x + u3.y;

        // reduce-scatter over slice bits (4 shfl total)
        float r0 = __shfl_xor_sync(0xffffffffu, bit2 ? p0 : p2, 4);
        float r1 = __shfl_xor_sync(0xffffffffu, bit2 ? p1 : p3, 4);
        if (!bit2) { p0 += r0; p1 += r1; } else { p2 += r0; p3 += r1; }
        float va = bit2 ? p2 : p0;
        float vb = bit2 ? p3 : p1;
        float r2 = __shfl_xor_sync(0xffffffffu, bit3 ? va : vb, 8);
        float v  = bit3 ? (vb + r2) : (va + r2);
        v += __shfl_xor_sync(0xffffffffu, v, 16);

        if (writer) {
            float pre = v + xp_cur;
            int tn = tcur + dt;
            tn = tn < 0 ? 0 : (tn >= TLEN ? TLEN - 1 : tn);
            xp_cur = xpb[(size_t)tn * EDIM + jw];    // next step's xp (redundant at end)
            float hv = tanhf(pre);
            *HDST = hv;
            if (MODE) {
                xoutF[obase + (size_t)tcur * EDIM + jw] = fmaxf(hv, 0.f);
            } else {
                __nv_bfloat16 hh = __float2bfloat16_rn(hv);
                xoutH[obase + (size_t)tcur * EDIM + jw] = hh;
                xoutL[obase + (size_t)tcur * EDIM + jw] =
                    __float2bfloat16_rn(hv - __bfloat162float(hh));
            }
        }
        __syncthreads();
    };

    int t = t0;
    for (int it = 0; it < TLEN / 2; it++) {
        step_body(hsA, hwB, t); t += dt;    // read A, write B
        step_body(hsB, hwA, t); t += dt;    // read B, write A
    }
}

// ---------------- 4) head input projection ----------------
__global__ __launch_bounds__(256) void head_proj(
    const float* __restrict__ x,
    const float* __restrict__ wi, const float* __restrict__ wf, const float* __restrict__ wc,
    const float* __restrict__ bii, const float* __restrict__ bhi,
    const float* __restrict__ bif, const float* __restrict__ bhf,
    const float* __restrict__ bic, const float* __restrict__ bhc,
    float* __restrict__ hxp)
{
    __shared__ float xs[16 * 516];
    int tid = threadIdx.x;
    int row0 = blockIdx.x * 16;

    for (int i = tid; i < 16 * 128; i += 256) {
        int r = i >> 7, c = i & 127;
        float4 v = reinterpret_cast<const float4*>(x + (size_t)(row0 + r) * 512)[c];
        *(float4*)&xs[r * 516 + c * 4] = v;
    }
    __syncthreads();

    int r = tid >> 4, c = tid & 15;
    if (c < 13) {
        const float* w;
        float bias;
        if (c < 3)      { w = wi + (size_t)c * 512;        bias = bii[c]     + bhi[c];     }
        else if (c < 8) { w = wf + (size_t)(c - 3) * 512;  bias = bif[c - 3] + bhf[c - 3]; }
        else            { w = wc + (size_t)(c - 8) * 512;  bias = bic[c - 8] + bhc[c - 8]; }
        float sum = 0.f;
        const float* xr = &xs[r * 516];
#pragma unroll 8
        for (int k = 0; k < 512; k += 4) {
            float4 wv = *(const float4*)&w[k];
            sum += xr[k] * wv.x + xr[k+1] * wv.y + xr[k+2] * wv.z + xr[k+3] * wv.w;
        }
        hxp[(size_t)(row0 + r) * 16 + c] = sum + bias;
    }
}

// ---------------- 5) head recurrences ----------------
__global__ __launch_bounds__(256) void head_rnn(
    const float* __restrict__ hxp,
    const float* __restrict__ whi, const float* __restrict__ whf, const float* __restrict__ whc,
    float* __restrict__ out)
{
    int wg   = (blockIdx.x * 256 + threadIdx.x) >> 5;   // 0..191
    int lane = threadIdx.x & 31;
    if (wg >= BATCH * 3) return;
    int b = wg / 3, head = wg - 3 * b;

    int C    = (head == 0) ? 3 : 5;
    int coff = (head == 0) ? 0 : ((head == 1) ? 3 : 8);
    const float* whh = (head == 0) ? whi : ((head == 1) ? whf : whc);
    size_t ooff = (head == 0) ? 0
                : ((head == 1) ? (size_t)NROWS * 3 : (size_t)NROWS * 8);

    float wr[5] = {0.f, 0.f, 0.f, 0.f, 0.f};
    if (lane < C) {
#pragma unroll
        for (int j = 0; j < 5; j++) if (j < C) wr[j] = whh[lane * C + j];
    }

    int xoffs = (lane < C) ? (coff + lane) : 0;
    const float* xb = hxp + (size_t)b * TLEN * 16 + xoffs;
    float*       ob = out + ooff + (size_t)b * TLEN * C + lane;

    float hv = 0.f;
    float Acur[8], Anxt[8];
#pragma unroll
    for (int i = 0; i < 8; i++) Acur[i] = xb[(size_t)i * 16];

    for (int tb = 0; tb < TLEN; tb += 8) {
        bool more = (tb + 8) < TLEN;
#pragma unroll
        for (int i = 0; i < 8; i++)
            Anxt[i] = more ? xb[(size_t)(tb + 8 + i) * 16] : 0.f;

#pragma unroll
        for (int i = 0; i < 8; i++) {
            float sum = Acur[i];
#pragma unroll
            for (int j = 0; j < 5; j++) {
                float hj = __shfl_sync(0xffffffffu, hv, j);
                sum += wr[j] * hj;
            }
            hv = tanhf(sum);
            if (lane < C) ob[(size_t)(tb + i) * C] = hv;
        }
#pragma unroll
        for (int i = 0; i < 8; i++) Acur[i] = Anxt[i];
    }
}

// ---------------- launch ----------------
extern "C" void kernel_launch(void* const* d_in, const int* in_sizes, int n_in,
                              void* d_out, int out_size)
{
    const int*   tokens = (const int*)  d_in[0];
    const float* emb    = (const float*)d_in[1];
    const float* w_ih   = (const float*)d_in[2];   // [2,2,256,512]
    const float* w_hh   = (const float*)d_in[3];   // [2,2,256,256]
    const float* b_ih   = (const float*)d_in[4];   // [2,2,256]
    const float* b_hh   = (const float*)d_in[5];
    const float* iwi = (const float*)d_in[6];
    const float* iwh = (const float*)d_in[7];
    const float* ibi = (const float*)d_in[8];
    const float* ibh = (const float*)d_in[9];
    const float* fwi = (const float*)d_in[10];
    const float* fwh = (const float*)d_in[11];
    const float* fbi = (const float*)d_in[12];
    const float* fbh = (const float*)d_in[13];
    const float* cwi = (const float*)d_in[14];
    const float* cwh = (const float*)d_in[15];
    const float* cbi = (const float*)d_in[16];
    const float* cbh = (const float*)d_in[17];
    float* out = (float*)d_out;

    float *px, *pxp, *phxp;
    __nv_bfloat16 *pahi, *palo, *pbhi, *pblo;
    cudaGetSymbolAddress((void**)&px,   g_x);
    cudaGetSymbolAddress((void**)&pxp,  g_xp);
    cudaGetSymbolAddress((void**)&phxp, g_hxp);
    cudaGetSymbolAddress((void**)&pahi, g_ahi);
    cudaGetSymbolAddress((void**)&palo, g_alo);
    cudaGetSymbolAddress((void**)&pbhi, g_bhi);
    cudaGetSymbolAddress((void**)&pblo, g_blo);

    cudaFuncSetAttribute(rnn_layer_t<0>, cudaFuncAttributeMaxDynamicSharedMemorySize, RNN_SMEM_BYTES);
    cudaFuncSetAttribute(rnn_layer_t<1>, cudaFuncAttributeMaxDynamicSharedMemorySize, RNN_SMEM_BYTES);
    cudaFuncSetAttribute(sgemm_mma, cudaFuncAttributeMaxDynamicSharedMemorySize, GM_SMEM);

    // layer 0
    wsplit<<<256, 256>>>(w_ih, pbhi, pblo);
    gather_split<<<(NROWS * 128) / 256, 256>>>(tokens, emb, pahi, palo);
    sgemm_mma<<<1024, GM_THREADS, GM_SMEM>>>(pahi, palo, pbhi, pblo, b_ih, b_hh, pxp);
    rnn_layer_t<0><<<128, 512, RNN_SMEM_BYTES>>>(pxp, w_hh, nullptr, pahi, palo);

    // layer 1 (relu fused into rnn output)
    wsplit<<<256, 256>>>(w_ih + (size_t)2 * HDIM * EDIM, pbhi, pblo);
    sgemm_mma<<<1024, GM_THREADS, GM_SMEM>>>(pahi, palo, pbhi, pblo,
                                             b_ih + 2 * HDIM, b_hh + 2 * HDIM, pxp);
    rnn_layer_t<1><<<128, 512, RNN_SMEM_BYTES>>>(pxp, w_hh + (size_t)2 * HDIM * HDIM,
                                                 px, nullptr, nullptr);

    // heads
    head_proj<<<NROWS / 16, 256>>>(px, iwi, fwi, cwi, ibi, ibh, fbi, fbh, cbi, cbh, phxp);
    head_rnn<<<24, 256>>>(phxp, iwh, fwh, cwh, out);
}